// round 1
// baseline (speedup 1.0000x reference)
#include <cuda_runtime.h>

#define HH 224
#define WW 224
#define CH 32
#define TM 4
#define NB 8

__global__ __launch_bounds__(256)
void persp_kernel(const float* __restrict__ in,
                  const float* __restrict__ wt,
                  float* __restrict__ out)
{
    const int j  = blockIdx.x * 32 + threadIdx.x;   // output W index (fast, coalesced stores)
    const int i  = blockIdx.y * 8  + threadIdx.y;   // output H index
    const int oc = blockIdx.z;                      // oc = c*TM + t
    const int c  = oc >> 2;
    const int t  = oc & 3;

    // Per-(t,c) 3x3 matrix (last entry implicitly 1). Broadcast LDG, L1-resident.
    const float* m = wt + ((t * CH) + c) * 8;
    const float m0 = m[0], m1 = m[1], m2 = m[2];
    const float m3 = m[3], m4 = m[4], m5 = m[5];
    const float m6 = m[6], m7 = m[7];

    // linspace(-1,1,224): x_lin indexed by i (H), y_lin by j (W) — the reference's
    // meshgrid('ij') + reshape convention.
    const float step = 2.0f / 223.0f;
    const float xl = fmaf((float)i, step, -1.0f);
    const float yl = fmaf((float)j, step, -1.0f);

    const float X = fmaf(m0, xl, fmaf(m1, yl, m2));
    const float Y = fmaf(m3, xl, fmaf(m4, yl, m5));
    const float O = fmaf(m6, xl, fmaf(m7, yl, 1.0f));
    const float r = 1.0f / O;          // accurate recip (no fast-math in harness build)
    const float xs = X * r;
    const float ys = Y * r;

    // x = 0.5*((x_s+1)*(max_x-1)), max_x-1 = 222
    const float x = 0.5f * ((xs + 1.0f) * 222.0f);
    const float y = 0.5f * ((ys + 1.0f) * 222.0f);

    const float fx0 = floorf(x);
    const float fy0 = floorf(y);
    int x0 = (int)fx0, x1 = x0 + 1;
    int y0 = (int)fy0, y1 = y0 + 1;
    x0 = min(max(x0, 0), WW - 1);
    x1 = min(max(x1, 0), WW - 1);
    y0 = min(max(y0, 0), HH - 1);
    y1 = min(max(y1, 0), HH - 1);
    const float x0f = (float)x0, x1f = (float)x1;
    const float y0f = (float)y0, y1f = (float)y1;

    // Reference's exact (quirky) weights: wb uses (y1f - y0f).
    const float wa = (x1f - x) * (y1f - y);
    const float wb = (x1f - x) * (y1f - y0f);
    const float wc = (x - x0f) * (y1f - y);
    const float wd = (x - x0f) * (y - y0f);

    const int plane = HH * WW;
    const int ba = y0 * WW + x0;   // gather row = y, col = x (near-transpose of (i,j))
    const int bb = y1 * WW + x0;
    const int bc = y0 * WW + x1;
    const int bd = y1 * WW + x1;

    const float* inp = in + (size_t)c * plane;
    float* op = out + (size_t)oc * plane + (size_t)i * WW + j;

    // Amortize coords over the batch: 4 gathers + 1 coalesced store per n.
    #pragma unroll
    for (int n = 0; n < NB; n++) {
        const float* p = inp + (size_t)n * CH * plane;
        const float Ia = __ldg(p + ba);
        const float Ib = __ldg(p + bb);
        const float Ic = __ldg(p + bc);
        const float Id = __ldg(p + bd);
        op[(size_t)n * TM * CH * plane] = wa * Ia + wb * Ib + wc * Ic + wd * Id;
    }
}

extern "C" void kernel_launch(void* const* d_in, const int* in_sizes, int n_in,
                              void* d_out, int out_size)
{
    const float* in = (const float*)d_in[0];   // inputs  (8,32,224,224) f32
    const float* wt = (const float*)d_in[1];   // wt_pers (4,32,8)       f32
    float* out = (float*)d_out;                // (8,128,224,224) f32

    dim3 block(32, 8);
    dim3 grid(WW / 32, HH / 8, CH * TM);
    persp_kernel<<<grid, block>>>(in, wt, out);
}

// round 5
// speedup vs baseline: 4.4159x; 4.4159x over previous
#include <cuda_runtime.h>

#define HH 224
#define WW 224
#define CH 32
#define TM 4
#define NB 8

// Tile transpose kernel:
//  - gather phase: warp lanes vary i (output H) -> gather x ~ i is contiguous -> coalesced LDG
//  - store  phase: via smem 32x33 transpose -> warp lanes vary j -> coalesced STG
__global__ __launch_bounds__(256)
void persp_kernel(const float* __restrict__ in,
                  const float* __restrict__ wt,
                  float* __restrict__ out)
{
    __shared__ float tile[32][33];   // [j_local][i_local], padded

    const int tx = threadIdx.x;      // i_local (gather-contiguous axis)
    const int ty = threadIdx.y;      // j_local group (4 j's per thread)
    const int j0 = blockIdx.x * 32;
    const int i0 = blockIdx.y * 32;
    const int oc = blockIdx.z;       // oc = c*TM + t
    const int c  = oc >> 2;
    const int t  = oc & 3;

    const float* m = wt + ((t * CH) + c) * 8;
    const float m0 = m[0], m1 = m[1], m2 = m[2];
    const float m3 = m[3], m4 = m[4], m5 = m[5];
    const float m6 = m[6], m7 = m[7];

    const float step = 2.0f / 223.0f;
    const int i = i0 + tx;
    const float xl = fmaf((float)i, step, -1.0f);   // linspace along H (i)

    // Per-pixel coordinates/weights, computed once, reused over the 8 batches.
    int   ba[4], dx[4], dyW[4];
    float wa[4], wb[4], wc[4], wd[4];

    #pragma unroll
    for (int k = 0; k < 4; k++) {
        const int j = j0 + ty * 4 + k;
        const float yl = fmaf((float)j, step, -1.0f);

        const float X = fmaf(m0, xl, fmaf(m1, yl, m2));
        const float Y = fmaf(m3, xl, fmaf(m4, yl, m5));
        const float O = fmaf(m6, xl, fmaf(m7, yl, 1.0f));
        const float r = 1.0f / O;
        const float xs = X * r;
        const float ys = Y * r;

        const float x = 0.5f * ((xs + 1.0f) * 222.0f);
        const float y = 0.5f * ((ys + 1.0f) * 222.0f);

        int x0 = (int)floorf(x), x1 = x0 + 1;
        int y0 = (int)floorf(y), y1 = y0 + 1;
        x0 = min(max(x0, 0), WW - 1);
        x1 = min(max(x1, 0), WW - 1);
        y0 = min(max(y0, 0), HH - 1);
        y1 = min(max(y1, 0), HH - 1);
        const float x0f = (float)x0, x1f = (float)x1;
        const float y0f = (float)y0, y1f = (float)y1;

        // Reference's exact (quirky) weights: wb uses (y1f - y0f).
        wa[k] = (x1f - x) * (y1f - y);
        wb[k] = (x1f - x) * (y1f - y0f);
        wc[k] = (x - x0f) * (y1f - y);
        wd[k] = (x - x0f) * (y - y0f);

        ba[k]  = y0 * WW + x0;        // gather: row = y (~j, near-constant per warp),
        dx[k]  = x1 - x0;             //         col = x (~i, contiguous across lanes)
        dyW[k] = (y1 - y0) * WW;
    }

    const int plane = HH * WW;
    const float* inp = in + (size_t)c * plane;
    float* op = out + (size_t)oc * plane;

    #pragma unroll
    for (int n = 0; n < NB; n++) {
        const float* p = inp + (size_t)n * CH * plane;

        // Gather phase: coalesced along lanes (tx -> x contiguous).
        #pragma unroll
        for (int k = 0; k < 4; k++) {
            const float Ia = __ldg(p + ba[k]);
            const float Ic = __ldg(p + ba[k] + dx[k]);
            const float Ib = __ldg(p + ba[k] + dyW[k]);
            const float Id = __ldg(p + ba[k] + dyW[k] + dx[k]);
            tile[ty * 4 + k][tx] = wa[k] * Ia + wb[k] * Ib + wc[k] * Ic + wd[k] * Id;
        }
        __syncthreads();

        // Store phase: transposed read from smem (stride-33, conflict-free),
        // coalesced STG along lanes (tx -> j contiguous).
        float* opn = op + (size_t)n * TM * CH * plane;
        #pragma unroll
        for (int k = 0; k < 4; k++) {
            const int ir = ty * 4 + k;
            opn[(size_t)(i0 + ir) * WW + j0 + tx] = tile[tx][ir];
        }
        __syncthreads();
    }
}

extern "C" void kernel_launch(void* const* d_in, const int* in_sizes, int n_in,
                              void* d_out, int out_size)
{
    const float* in = (const float*)d_in[0];   // inputs  (8,32,224,224) f32
    const float* wt = (const float*)d_in[1];   // wt_pers (4,32,8)       f32
    float* out = (float*)d_out;                // (8,128,224,224) f32

    dim3 block(32, 8);
    dim3 grid(WW / 32, WW / 32, CH * TM);      // 7 x 7 x 128
    persp_kernel<<<grid, block>>>(in, wt, out);
}

// round 7
// speedup vs baseline: 4.5079x; 1.0208x over previous
#include <cuda_runtime.h>

#define HH 224
#define WW 224
#define CH 32
#define TM 4
#define NB 8

// One pixel per thread, 32x32 tile, double-buffered smem transpose.
//  - gather phase: lanes (tx) vary i -> gather x ~ i contiguous -> coalesced LDG
//  - store  phase: lanes (tx) vary j -> coalesced STG, via smem [j][i] tile (pad 33)
__global__ __launch_bounds__(1024, 1)
void persp_kernel(const float* __restrict__ in,
                  const float* __restrict__ wt,
                  float* __restrict__ out)
{
    __shared__ float tile[2][32][33];   // [buf][j_local][i_local]

    const int tx = threadIdx.x;         // gather: i_local | store: j_local
    const int ty = threadIdx.y;         // gather: j_local | store: i_local
    const int j0 = blockIdx.x * 32;
    const int i0 = blockIdx.y * 32;
    const int oc = blockIdx.z;          // oc = c*TM + t
    const int c  = oc >> 2;
    const int t  = oc & 3;

    const float* m = wt + ((t * CH) + c) * 8;
    const float m0 = m[0], m1 = m[1], m2 = m[2];
    const float m3 = m[3], m4 = m[4], m5 = m[5];
    const float m6 = m[6], m7 = m[7];

    const float step = 2.0f / 223.0f;
    const int i = i0 + tx;
    const int j = j0 + ty;
    const float xl = fmaf((float)i, step, -1.0f);   // linspace along H (i)
    const float yl = fmaf((float)j, step, -1.0f);   // linspace along W (j)

    const float X = fmaf(m0, xl, fmaf(m1, yl, m2));
    const float Y = fmaf(m3, xl, fmaf(m4, yl, m5));
    const float O = fmaf(m6, xl, fmaf(m7, yl, 1.0f));
    const float r = 1.0f / O;                       // accurate recip
    const float xs = X * r;
    const float ys = Y * r;

    const float x = 0.5f * ((xs + 1.0f) * 222.0f);
    const float y = 0.5f * ((ys + 1.0f) * 222.0f);

    int x0 = (int)floorf(x), x1 = x0 + 1;
    int y0 = (int)floorf(y), y1 = y0 + 1;
    x0 = min(max(x0, 0), WW - 1);
    x1 = min(max(x1, 0), WW - 1);
    y0 = min(max(y0, 0), HH - 1);
    y1 = min(max(y1, 0), HH - 1);
    const float x0f = (float)x0, x1f = (float)x1;
    const float y0f = (float)y0, y1f = (float)y1;

    // Reference's exact (quirky) weights: wb uses (y1f - y0f).
    const float wa = (x1f - x) * (y1f - y);
    const float wb = (x1f - x) * (y1f - y0f);
    const float wc = (x - x0f) * (y1f - y);
    const float wd = (x - x0f) * (y - y0f);

    const int ba  = y0 * WW + x0;   // gather: row = y (~j, warp-uniform-ish),
    const int dx  = x1 - x0;        //         col = x (~i, contiguous across lanes)
    const int dyW = (y1 - y0) * WW;

    const int plane = HH * WW;
    const float* inp = in + (size_t)c * plane;
    // Store-phase output element for this thread: (i' = i0+ty, j' = j0+tx)
    float* op = out + (size_t)oc * plane + (size_t)(i0 + ty) * WW + (j0 + tx);

    #pragma unroll 2
    for (int n = 0; n < NB; n++) {
        const float* p = inp + (size_t)n * CH * plane;
        const int buf = n & 1;

        // Gather (coalesced along lanes: x contiguous)
        const float Ia = __ldg(p + ba);
        const float Ic = __ldg(p + ba + dx);
        const float Ib = __ldg(p + ba + dyW);
        const float Id = __ldg(p + ba + dyW + dx);
        tile[buf][ty][tx] = wa * Ia + wb * Ib + wc * Ic + wd * Id;

        // Single barrier per iter: publishes tile[buf] for the store phase AND
        // (from iter n-1's barrier) guarantees stores of buf finished before
        // this iteration's gather overwrote it.
        __syncthreads();

        // Store (coalesced along lanes: j contiguous). LDS stride-33: conflict-free.
        op[(size_t)n * TM * CH * plane] = tile[buf][tx][ty];
    }
}

extern "C" void kernel_launch(void* const* d_in, const int* in_sizes, int n_in,
                              void* d_out, int out_size)
{
    const float* in = (const float*)d_in[0];   // inputs  (8,32,224,224) f32
    const float* wt = (const float*)d_in[1];   // wt_pers (4,32,8)       f32
    float* out = (float*)d_out;                // (8,128,224,224) f32

    dim3 block(32, 32);
    dim3 grid(WW / 32, HH / 32, CH * TM);      // 7 x 7 x 128
    persp_kernel<<<grid, block>>>(in, wt, out);
}

// round 9
// speedup vs baseline: 5.1885x; 1.1510x over previous
#include <cuda_runtime.h>

#define HH 224
#define WW 224
#define CH 32
#define TM 4
#define NB 8

// Block (32,16) = 512 threads handles one 32x32 output tile for one (t,c).
// Each thread: 2 j-pixels (ty, ty+16). Phases of 2 batch-planes, 4-buffer smem
// rotation -> one __syncthreads per phase (4 total). Store phase uses STG.128.
__global__ __launch_bounds__(512)
void persp_kernel(const float* __restrict__ in,
                  const float* __restrict__ wt,
                  float* __restrict__ out)
{
    __shared__ float tile[4][32][33];   // [buf][j_local][i_local], pad 33

    const int tx  = threadIdx.x;        // i_local (gather-contiguous axis)
    const int ty  = threadIdx.y;        // j_local base (handles ty and ty+16)
    const int tid = ty * 32 + tx;
    const int j0 = blockIdx.x * 32;
    const int i0 = blockIdx.y * 32;
    const int oc = blockIdx.z;          // oc = c*TM + t
    const int c  = oc >> 2;
    const int t  = oc & 3;

    const float* m = wt + ((t * CH) + c) * 8;
    const float m0 = m[0], m1 = m[1], m2 = m[2];
    const float m3 = m[3], m4 = m[4], m5 = m[5];
    const float m6 = m[6], m7 = m[7];

    const float step = 2.0f / 223.0f;
    const int i = i0 + tx;
    const float xl = fmaf((float)i, step, -1.0f);   // linspace along H (i)

    // Per-pixel state for the 2 j-halves this thread owns.
    int   o0[2], o1[2], o2[2], o3[2];
    float wa[2], wb[2], wc[2], wd[2];

    #pragma unroll
    for (int h = 0; h < 2; h++) {
        const int j = j0 + ty + 16 * h;
        const float yl = fmaf((float)j, step, -1.0f);

        const float X = fmaf(m0, xl, fmaf(m1, yl, m2));
        const float Y = fmaf(m3, xl, fmaf(m4, yl, m5));
        const float O = fmaf(m6, xl, fmaf(m7, yl, 1.0f));
        const float r = 1.0f / O;                   // accurate recip
        const float xs = X * r;
        const float ys = Y * r;

        const float x = 0.5f * ((xs + 1.0f) * 222.0f);
        const float y = 0.5f * ((ys + 1.0f) * 222.0f);

        int x0 = (int)floorf(x), x1 = x0 + 1;
        int y0 = (int)floorf(y), y1 = y0 + 1;
        x0 = min(max(x0, 0), WW - 1);
        x1 = min(max(x1, 0), WW - 1);
        y0 = min(max(y0, 0), HH - 1);
        y1 = min(max(y1, 0), HH - 1);
        const float x0f = (float)x0, x1f = (float)x1;
        const float y0f = (float)y0, y1f = (float)y1;

        // Reference's exact (quirky) weights: wb uses (y1f - y0f).
        wa[h] = (x1f - x) * (y1f - y);
        wb[h] = (x1f - x) * (y1f - y0f);
        wc[h] = (x - x0f) * (y1f - y);
        wd[h] = (x - x0f) * (y - y0f);

        const int ba  = y0 * WW + x0;
        const int dx  = x1 - x0;
        const int dyW = (y1 - y0) * WW;
        o0[h] = ba;
        o1[h] = ba + dx;
        o2[h] = ba + dyW;
        o3[h] = ba + dyW + dx;
    }

    const int plane = HH * WW;
    const float* inp = in + (size_t)c * plane;

    // Store-phase assignment: 512 threads -> 512 STG.128 per phase.
    const int n_sub = tid >> 8;          // which of the 2 planes in the phase
    const int rem   = tid & 255;
    const int i_loc = rem >> 3;          // 0..31
    const int jc    = rem & 7;           // float4 chunk along j
    float* oq = out + (size_t)oc * plane
                    + (size_t)(i0 + i_loc) * WW + (j0 + 4 * jc);

    #pragma unroll
    for (int ph = 0; ph < NB / 2; ph++) {
        const int pair = (ph & 1) * 2;   // smem buffer pair for this phase

        // ---- Gather: 2 planes x 2 j-halves x 4 corners = 16 LDG in flight ----
        float v[2][2][4];
        #pragma unroll
        for (int nn = 0; nn < 2; nn++) {
            const float* p = inp + (size_t)(2 * ph + nn) * CH * plane;
            #pragma unroll
            for (int h = 0; h < 2; h++) {
                v[nn][h][0] = __ldg(p + o0[h]);
                v[nn][h][1] = __ldg(p + o1[h]);
                v[nn][h][2] = __ldg(p + o2[h]);
                v[nn][h][3] = __ldg(p + o3[h]);
            }
        }
        #pragma unroll
        for (int nn = 0; nn < 2; nn++) {
            #pragma unroll
            for (int h = 0; h < 2; h++) {
                tile[pair + nn][ty + 16 * h][tx] =
                    wa[h] * v[nn][h][0] + wb[h] * v[nn][h][2] +
                    wc[h] * v[nn][h][1] + wd[h] * v[nn][h][3];
            }
        }

        // One barrier per phase: publishes this pair; the previous phase's
        // stores (other pair) completed before this barrier, so phase ph+2
        // may safely overwrite that pair after its own barrier.
        __syncthreads();

        // ---- Store: transposed read (conflict-free), STG.128 coalesced ----
        const int n = 2 * ph + n_sub;
        float4 r4;
        r4.x = tile[pair + n_sub][4 * jc + 0][i_loc];
        r4.y = tile[pair + n_sub][4 * jc + 1][i_loc];
        r4.z = tile[pair + n_sub][4 * jc + 2][i_loc];
        r4.w = tile[pair + n_sub][4 * jc + 3][i_loc];
        *(float4*)(oq + (size_t)n * TM * CH * plane) = r4;
    }
}

extern "C" void kernel_launch(void* const* d_in, const int* in_sizes, int n_in,
                              void* d_out, int out_size)
{
    const float* in = (const float*)d_in[0];   // inputs  (8,32,224,224) f32
    const float* wt = (const float*)d_in[1];   // wt_pers (4,32,8)       f32
    float* out = (float*)d_out;                // (8,128,224,224) f32

    dim3 block(32, 16);
    dim3 grid(WW / 32, HH / 32, CH * TM);      // 7 x 7 x 128
    persp_kernel<<<grid, block>>>(in, wt, out);
}